// round 11
// baseline (speedup 1.0000x reference)
#include <cuda_runtime.h>
#include <math.h>

// out = sign(x @ sign(W)) : fp32 GEMM with per-output single-accumulator,
// k-ascending RN-FMA chains (bit-matches cublas/Eigen/oneDNN fp32 reference order).
// Compute uses packed fma.rn.f32x2 (sm_103a): 2 independent IEEE fp32 lanes
// per instruction -> 2x FFMA throughput, identical per-lane rounding.
// M=8192, K=2048, N=2048.

#define BM 128
#define BN 128
#define BK 16
#define TM 8
#define TN 8
#define NTHREADS 256

__device__ __forceinline__ float sgnf(float v) {
    return (v > 0.0f) ? 1.0f : ((v < 0.0f) ? -1.0f : 0.0f);
}

__device__ __forceinline__ unsigned long long pack_dup(float x) {
    unsigned long long r;
    asm("mov.b64 %0, {%1, %1};" : "=l"(r) : "f"(x));
    return r;
}

__device__ __forceinline__ void fma2(unsigned long long& d,
                                     unsigned long long a,
                                     unsigned long long b) {
    asm("fma.rn.f32x2 %0, %1, %2, %0;" : "+l"(d) : "l"(a), "l"(b));
}

__device__ __forceinline__ float2 unpack2(unsigned long long v) {
    float2 r;
    asm("mov.b64 {%0, %1}, %2;" : "=f"(r.x), "=f"(r.y) : "l"(v));
    return r;
}

__global__ __launch_bounds__(NTHREADS)
void binary_gemm_kernel(const float* __restrict__ X,   // [M, K] row-major
                        const float* __restrict__ W,   // [K, N] row-major
                        float* __restrict__ O,         // [M, N] row-major
                        int M, int N, int K)
{
    __shared__ float As[2][BK][BM];   // transposed A tiles (double buffer)
    __shared__ float Bs[2][BK][BN];   // binarized B tiles  (double buffer)

    const int bx = blockIdx.x;
    const int by = blockIdx.y;
    const int tid = threadIdx.x;
    const int tx = tid % 16;
    const int ty = tid / 16;

    const float* Xblk = X + (size_t)by * BM * K;
    const float* Wblk = W + (size_t)bx * BN;

    // acc pairs: lane0 = col j, lane1 = col j+1 (each lane its own k-chain)
    unsigned long long acc2[TM][TN / 2];
    #pragma unroll
    for (int i = 0; i < TM; i++)
        #pragma unroll
        for (int j = 0; j < TN / 2; j++)
            acc2[i][j] = 0ULL;

    const int arow  = tid >> 2;
    const int acol4 = (tid & 3) * 4;
    const int brow  = tid >> 5;
    const int bcol4 = (tid & 31) * 4;

    const float* aptr0 = Xblk + (size_t)arow * K + acol4;
    const float* aptr1 = Xblk + (size_t)(arow + 64) * K + acol4;
    const float* bptr0 = Wblk + (size_t)brow * N + bcol4;
    const float* bptr1 = Wblk + (size_t)(brow + 8) * N + bcol4;

    // ---- prologue: tile 0 -> buffer 0 ----
    {
        float4 va0 = *reinterpret_cast<const float4*>(aptr0);
        float4 va1 = *reinterpret_cast<const float4*>(aptr1);
        float4 vb0 = *reinterpret_cast<const float4*>(bptr0);
        float4 vb1 = *reinterpret_cast<const float4*>(bptr1);
        As[0][acol4 + 0][arow] = va0.x;
        As[0][acol4 + 1][arow] = va0.y;
        As[0][acol4 + 2][arow] = va0.z;
        As[0][acol4 + 3][arow] = va0.w;
        As[0][acol4 + 0][arow + 64] = va1.x;
        As[0][acol4 + 1][arow + 64] = va1.y;
        As[0][acol4 + 2][arow + 64] = va1.z;
        As[0][acol4 + 3][arow + 64] = va1.w;
        float4 s0, s1;
        s0.x = sgnf(vb0.x); s0.y = sgnf(vb0.y); s0.z = sgnf(vb0.z); s0.w = sgnf(vb0.w);
        s1.x = sgnf(vb1.x); s1.y = sgnf(vb1.y); s1.z = sgnf(vb1.z); s1.w = sgnf(vb1.w);
        *reinterpret_cast<float4*>(&Bs[0][brow][bcol4]) = s0;
        *reinterpret_cast<float4*>(&Bs[0][brow + 8][bcol4]) = s1;
    }
    __syncthreads();

    int buf = 0;
    for (int kt = 0; kt < K; kt += BK) {
        const int knext = kt + BK;
        float4 va0, va1, vb0, vb1;
        const bool has_next = (knext < K);
        if (has_next) {
            va0 = *reinterpret_cast<const float4*>(aptr0 + knext);
            va1 = *reinterpret_cast<const float4*>(aptr1 + knext);
            vb0 = *reinterpret_cast<const float4*>(bptr0 + (size_t)knext * N);
            vb1 = *reinterpret_cast<const float4*>(bptr1 + (size_t)knext * N);
        }

        // ---- compute: k ascending, one f32x2 FMA per (output-pair, k) ----
        #pragma unroll
        for (int k = 0; k < BK; k++) {
            float4 a0 = *reinterpret_cast<const float4*>(&As[buf][k][ty * TM]);
            float4 a1 = *reinterpret_cast<const float4*>(&As[buf][k][ty * TM + 4]);
            // b pairs: consecutive floats reinterpreted as packed f32x2
            ulonglong2 p0 = *reinterpret_cast<const ulonglong2*>(&Bs[buf][k][tx * TN]);
            ulonglong2 p1 = *reinterpret_cast<const ulonglong2*>(&Bs[buf][k][tx * TN + 4]);
            unsigned long long b2[4] = {p0.x, p0.y, p1.x, p1.y};
            float a[TM] = {a0.x, a0.y, a0.z, a0.w, a1.x, a1.y, a1.z, a1.w};
            #pragma unroll
            for (int i = 0; i < TM; i++) {
                unsigned long long aa = pack_dup(a[i]);
                #pragma unroll
                for (int j = 0; j < TN / 2; j++)
                    fma2(acc2[i][j], aa, b2[j]);
            }
        }

        if (has_next) {
            const int nb = buf ^ 1;
            As[nb][acol4 + 0][arow] = va0.x;
            As[nb][acol4 + 1][arow] = va0.y;
            As[nb][acol4 + 2][arow] = va0.z;
            As[nb][acol4 + 3][arow] = va0.w;
            As[nb][acol4 + 0][arow + 64] = va1.x;
            As[nb][acol4 + 1][arow + 64] = va1.y;
            As[nb][acol4 + 2][arow + 64] = va1.z;
            As[nb][acol4 + 3][arow + 64] = va1.w;
            float4 s0, s1;
            s0.x = sgnf(vb0.x); s0.y = sgnf(vb0.y); s0.z = sgnf(vb0.z); s0.w = sgnf(vb0.w);
            s1.x = sgnf(vb1.x); s1.y = sgnf(vb1.y); s1.z = sgnf(vb1.z); s1.w = sgnf(vb1.w);
            *reinterpret_cast<float4*>(&Bs[nb][brow][bcol4]) = s0;
            *reinterpret_cast<float4*>(&Bs[nb][brow + 8][bcol4]) = s1;
            __syncthreads();
            buf = nb;
        }
    }

    // ---- epilogue: unpack, sign, store ----
    float* Oblk = O + (size_t)by * BM * N + (size_t)bx * BN;
    #pragma unroll
    for (int i = 0; i < TM; i++) {
        float* orow = Oblk + (size_t)(ty * TM + i) * N + tx * TN;
        float2 u0 = unpack2(acc2[i][0]);
        float2 u1 = unpack2(acc2[i][1]);
        float2 u2 = unpack2(acc2[i][2]);
        float2 u3 = unpack2(acc2[i][3]);
        float4 v0, v1;
        v0.x = sgnf(u0.x); v0.y = sgnf(u0.y); v0.z = sgnf(u1.x); v0.w = sgnf(u1.y);
        v1.x = sgnf(u2.x); v1.y = sgnf(u2.y); v1.z = sgnf(u3.x); v1.w = sgnf(u3.y);
        *reinterpret_cast<float4*>(orow) = v0;
        *reinterpret_cast<float4*>(orow + 4) = v1;
    }
}

extern "C" void kernel_launch(void* const* d_in, const int* in_sizes, int n_in,
                              void* d_out, int out_size) {
    const float* x = (const float*)d_in[0];      // [M, K]
    const float* w = (const float*)d_in[1];      // [K, N] (square)
    float* out = (float*)d_out;                  // [M, N]

    int K = 1;
    {
        long long kw = in_sizes[1];
        long long r = (long long)(sqrt((double)kw));
        while (r * r < kw) r++;
        while (r * r > kw) r--;
        K = (int)r;
    }
    int N = (int)(in_sizes[1] / K);
    int M = (int)(in_sizes[0] / K);

    dim3 grid(N / BN, M / BM);
    dim3 block(NTHREADS);
    binary_gemm_kernel<<<grid, block>>>(x, w, out, M, N, K);
}